// round 1
// baseline (speedup 1.0000x reference)
#include <cuda_runtime.h>

// ---------------------------------------------------------------------------
// ViSNeRF fused sampler: channel-last transposed planes + fused bilinear/line
// gather + 19x32 matvec.
// ---------------------------------------------------------------------------

#define RES   512
#define NCOMP 16
#define NOUT  32
#define NIN   19   // 16 coef + 3 pfeat

// Scratch (allocation-free rule: __device__ globals).
// planes transposed to [3][512][512][16]  (channel-last, 48 MB)
static __device__ float g_planeT[3 * RES * RES * NCOMP];
// lines transposed to [3][512][16]
static __device__ float g_lineT[3 * RES * NCOMP];

// ---- transpose planes [p][c][y][x] -> [p][y][x][c] -------------------------
__global__ void k_transpose_planes(const float* __restrict__ planes) {
    int t = blockIdx.x * blockDim.x + threadIdx.x;
    const int HW = RES * RES;
    if (t >= 3 * HW) return;
    int p  = t / HW;
    int yx = t - p * HW;
    float v[NCOMP];
#pragma unroll
    for (int c = 0; c < NCOMP; ++c)
        v[c] = planes[(size_t)(p * NCOMP + c) * HW + yx];
    float4* dst = reinterpret_cast<float4*>(g_planeT + (size_t)t * NCOMP);
#pragma unroll
    for (int j = 0; j < 4; ++j)
        dst[j] = make_float4(v[4*j+0], v[4*j+1], v[4*j+2], v[4*j+3]);
}

// ---- transpose lines [p][c][y] -> [p][y][c] --------------------------------
__global__ void k_transpose_lines(const float* __restrict__ lines) {
    int t = blockIdx.x * blockDim.x + threadIdx.x;
    if (t >= 3 * RES) return;
    int p = t / RES;
    int y = t - p * RES;
#pragma unroll
    for (int c = 0; c < NCOMP; ++c)
        g_lineT[t * NCOMP + c] = lines[(p * NCOMP + c) * RES + y];
}

// ---- main fused kernel ------------------------------------------------------
__global__ void __launch_bounds__(256) k_visnerf(
    const float* __restrict__ pts,      // [N,3]
    const float* __restrict__ ts,       // [N,1]
    const float* __restrict__ params,   // [3,3]
    const float* __restrict__ W,        // [32,19] row-major (out, in)
    float*       __restrict__ out,      // [N,32]
    int n)
{
    __shared__ float sW[NOUT * NIN];
    for (int i = threadIdx.x; i < NOUT * NIN; i += blockDim.x) sW[i] = W[i];
    __syncthreads();

    int i = blockIdx.x * blockDim.x + threadIdx.x;
    if (i >= n) return;

    const float B  = 1.3f;
    const float sc = 2.0f / (-2.0f * B);

    float pn[3];
#pragma unroll
    for (int d = 0; d < 3; ++d)
        pn[d] = (pts[(size_t)i * 3 + d] - B) * sc - 1.0f;

    float4 coef[4];
#pragma unroll
    for (int j = 0; j < 4; ++j) coef[j] = make_float4(0.f, 0.f, 0.f, 0.f);

    const int MX[3] = {0, 0, 1};
    const int MY[3] = {1, 2, 2};
    const int VM[3] = {2, 1, 0};

#pragma unroll
    for (int p = 0; p < 3; ++p) {
        float gx = pn[MX[p]];
        float gy = pn[MY[p]];
        float lc = pn[VM[p]];

        // bilinear setup (align_corners=True semantics)
        float ix = (gx + 1.0f) * 0.5f * (float)(RES - 1);
        float iy = (gy + 1.0f) * 0.5f * (float)(RES - 1);
        float fx = floorf(ix), fy = floorf(iy);
        float wx = ix - fx,   wy = iy - fy;
        int x0 = min(max((int)fx, 0), RES - 1);
        int x1 = min(x0 + 1, RES - 1);
        int y0 = min(max((int)fy, 0), RES - 1);
        int y1 = min(y0 + 1, RES - 1);
        float w00 = (1.0f - wy) * (1.0f - wx);
        float w01 = (1.0f - wy) * wx;
        float w10 = wy * (1.0f - wx);
        float w11 = wy * wx;

        const float4* c00 = reinterpret_cast<const float4*>(
            g_planeT + (size_t)((p * RES + y0) * RES + x0) * NCOMP);
        const float4* c01 = reinterpret_cast<const float4*>(
            g_planeT + (size_t)((p * RES + y0) * RES + x1) * NCOMP);
        const float4* c10 = reinterpret_cast<const float4*>(
            g_planeT + (size_t)((p * RES + y1) * RES + x0) * NCOMP);
        const float4* c11 = reinterpret_cast<const float4*>(
            g_planeT + (size_t)((p * RES + y1) * RES + x1) * NCOMP);

        // line setup
        float il = (lc + 1.0f) * 0.5f * (float)(RES - 1);
        float fl = floorf(il);
        float wl = il - fl;
        int l0 = min(max((int)fl, 0), RES - 1);
        int l1 = min(l0 + 1, RES - 1);
        const float4* L0 = reinterpret_cast<const float4*>(
            g_lineT + (size_t)(p * RES + l0) * NCOMP);
        const float4* L1 = reinterpret_cast<const float4*>(
            g_lineT + (size_t)(p * RES + l1) * NCOMP);

#pragma unroll
        for (int j = 0; j < 4; ++j) {
            float4 a = __ldg(c00 + j);
            float4 b = __ldg(c01 + j);
            float4 c = __ldg(c10 + j);
            float4 d = __ldg(c11 + j);
            float4 pv;
            pv.x = fmaf(a.x, w00, fmaf(b.x, w01, fmaf(c.x, w10, d.x * w11)));
            pv.y = fmaf(a.y, w00, fmaf(b.y, w01, fmaf(c.y, w10, d.y * w11)));
            pv.z = fmaf(a.z, w00, fmaf(b.z, w01, fmaf(c.z, w10, d.z * w11)));
            pv.w = fmaf(a.w, w00, fmaf(b.w, w01, fmaf(c.w, w10, d.w * w11)));

            float4 u = __ldg(L0 + j);
            float4 v = __ldg(L1 + j);
            float4 lv;
            lv.x = fmaf(u.x, 1.0f - wl, v.x * wl);
            lv.y = fmaf(u.y, 1.0f - wl, v.y * wl);
            lv.z = fmaf(u.z, 1.0f - wl, v.z * wl);
            lv.w = fmaf(u.w, 1.0f - wl, v.w * wl);

            coef[j].x = fmaf(pv.x, lv.x, coef[j].x);
            coef[j].y = fmaf(pv.y, lv.y, coef[j].y);
            coef[j].z = fmaf(pv.z, lv.z, coef[j].z);
            coef[j].w = fmaf(pv.w, lv.w, coef[j].w);
        }
    }

    // pfeat = _sample1d(params_grid [3,3], t)
    float t  = ts[i];
    float it = (t + 1.0f) * 0.5f * 2.0f;
    float ft = floorf(it);
    float wt = it - ft;
    int a0 = min(max((int)ft, 0), 2);
    int a1 = min(a0 + 1, 2);
    float pf[3];
#pragma unroll
    for (int j = 0; j < 3; ++j)
        pf[j] = fmaf(__ldg(&params[j * 3 + a0]), 1.0f - wt,
                     __ldg(&params[j * 3 + a1]) * wt);

    float cf[NCOMP];
#pragma unroll
    for (int j = 0; j < 4; ++j) {
        cf[4*j+0] = coef[j].x;
        cf[4*j+1] = coef[j].y;
        cf[4*j+2] = coef[j].z;
        cf[4*j+3] = coef[j].w;
    }

    // out[i, :] = feats @ W.T  (feats = [cf(16), pf(3)])
    float* op = out + (size_t)i * NOUT;
#pragma unroll
    for (int o4 = 0; o4 < NOUT / 4; ++o4) {
        float4 r;
        float* rr = reinterpret_cast<float*>(&r);
#pragma unroll
        for (int k = 0; k < 4; ++k) {
            int o = o4 * 4 + k;
            float acc = 0.0f;
#pragma unroll
            for (int c = 0; c < NCOMP; ++c)
                acc = fmaf(cf[c], sW[o * NIN + c], acc);
#pragma unroll
            for (int j = 0; j < 3; ++j)
                acc = fmaf(pf[j], sW[o * NIN + NCOMP + j], acc);
            rr[k] = acc;
        }
        reinterpret_cast<float4*>(op)[o4] = r;
    }
}

// ---------------------------------------------------------------------------
extern "C" void kernel_launch(void* const* d_in, const int* in_sizes, int n_in,
                              void* d_out, int out_size) {
    const float* pts    = (const float*)d_in[0];
    const float* ts     = (const float*)d_in[1];
    const float* planes = (const float*)d_in[2];
    const float* lines  = (const float*)d_in[3];
    const float* params = (const float*)d_in[4];
    const float* W      = (const float*)d_in[5];
    float* out = (float*)d_out;

    int n = in_sizes[0] / 3;

    k_transpose_planes<<<(3 * RES * RES + 255) / 256, 256>>>(planes);
    k_transpose_lines<<<(3 * RES + 255) / 256, 256>>>(lines);
    k_visnerf<<<(n + 255) / 256, 256>>>(pts, ts, params, W, out, n);
}

// round 2
// speedup vs baseline: 1.7127x; 1.7127x over previous
#include <cuda_runtime.h>
#include <cuda_fp16.h>

// ---------------------------------------------------------------------------
// ViSNeRF fused sampler, round 2: fp16 channel-last planes/lines (halves
// gather wavefronts), fp32 compute, shared-staged coalesced pts/ts loads.
// ---------------------------------------------------------------------------

#define RES   512
#define NCOMP 16
#define NOUT  32
#define NIN   19   // 16 coef + 3 pfeat

// One pixel = 16 halfs = 32 B = 2 uint4.
// planes: [3][512][512] pixels (+pad so the x0=511 pair-load never faults)
static __device__ uint4 g_planeH[3 * RES * RES * 2 + 4];
// lines: [3][512] pixels (+pad)
static __device__ uint4 g_lineH[3 * RES * 2 + 4];

// ---- transpose+quantize planes [p][c][y][x] fp32 -> [p][y][x][c] fp16 ------
__global__ void k_transpose_planes(const float* __restrict__ planes) {
    int t = blockIdx.x * blockDim.x + threadIdx.x;
    const int HW = RES * RES;
    if (t >= 3 * HW) return;
    int p  = t / HW;
    int yx = t - p * HW;
    __half2 h[8];
#pragma unroll
    for (int k = 0; k < 8; ++k) {
        float a = planes[(size_t)(p * NCOMP + 2 * k)     * HW + yx];
        float b = planes[(size_t)(p * NCOMP + 2 * k + 1) * HW + yx];
        h[k] = __floats2half2_rn(a, b);
    }
    uint4* dst = g_planeH + (size_t)t * 2;
    dst[0] = *reinterpret_cast<uint4*>(&h[0]);
    dst[1] = *reinterpret_cast<uint4*>(&h[4]);
}

// ---- transpose+quantize lines [p][c][y] -> [p][y][c] fp16 -------------------
__global__ void k_transpose_lines(const float* __restrict__ lines) {
    int t = blockIdx.x * blockDim.x + threadIdx.x;
    if (t >= 3 * RES) return;
    int p = t / RES;
    int y = t - p * RES;
    __half2 h[8];
#pragma unroll
    for (int k = 0; k < 8; ++k) {
        float a = lines[(p * NCOMP + 2 * k)     * RES + y];
        float b = lines[(p * NCOMP + 2 * k + 1) * RES + y];
        h[k] = __floats2half2_rn(a, b);
    }
    uint4* dst = g_lineH + (size_t)t * 2;
    dst[0] = *reinterpret_cast<uint4*>(&h[0]);
    dst[1] = *reinterpret_cast<uint4*>(&h[4]);
}

// ---- main fused kernel ------------------------------------------------------
__global__ void __launch_bounds__(256) k_visnerf(
    const float* __restrict__ pts,      // [N,3]
    const float* __restrict__ ts,       // [N,1]
    const float* __restrict__ params,   // [3,3]
    const float* __restrict__ W,        // [32,19]
    float*       __restrict__ out,      // [N,32]
    int n)
{
    __shared__ float sW[NOUT * NIN];
    __shared__ float s_pts[256 * 3];
    __shared__ float s_ts[256];

    for (int i = threadIdx.x; i < NOUT * NIN; i += blockDim.x) sW[i] = W[i];

    int base = blockIdx.x * 256;
    if (base + 256 <= n) {
        // fully coalesced float4 staging
        const float4* gp = reinterpret_cast<const float4*>(pts + (size_t)base * 3);
        if (threadIdx.x < 192)
            reinterpret_cast<float4*>(s_pts)[threadIdx.x] = gp[threadIdx.x];
        const float4* gt = reinterpret_cast<const float4*>(ts + base);
        if (threadIdx.x < 64)
            reinterpret_cast<float4*>(s_ts)[threadIdx.x] = gt[threadIdx.x];
    } else {
        int i = base + threadIdx.x;
        if (i < n) {
            s_pts[threadIdx.x * 3 + 0] = pts[(size_t)i * 3 + 0];
            s_pts[threadIdx.x * 3 + 1] = pts[(size_t)i * 3 + 1];
            s_pts[threadIdx.x * 3 + 2] = pts[(size_t)i * 3 + 2];
            s_ts[threadIdx.x] = ts[i];
        }
    }
    __syncthreads();

    int i = base + threadIdx.x;
    if (i >= n) return;

    const float B  = 1.3f;
    const float sc = 2.0f / (-2.0f * B);

    float pn[3];
#pragma unroll
    for (int d = 0; d < 3; ++d)
        pn[d] = (s_pts[threadIdx.x * 3 + d] - B) * sc - 1.0f;

    float2 coef[8];
#pragma unroll
    for (int k = 0; k < 8; ++k) coef[k] = make_float2(0.f, 0.f);

    const int MX[3] = {0, 0, 1};
    const int MY[3] = {1, 2, 2};
    const int VM[3] = {2, 1, 0};

#pragma unroll
    for (int p = 0; p < 3; ++p) {
        float gx = pn[MX[p]];
        float gy = pn[MY[p]];
        float lc = pn[VM[p]];

        float ix = (gx + 1.0f) * 0.5f * (float)(RES - 1);
        float iy = (gy + 1.0f) * 0.5f * (float)(RES - 1);
        float fx = floorf(ix), fy = floorf(iy);
        float wx = ix - fx,   wy = iy - fy;
        int x0 = min(max((int)fx, 0), RES - 1);
        int y0 = min(max((int)fy, 0), RES - 1);
        int y1 = min(y0 + 1, RES - 1);
        float w00 = (1.0f - wy) * (1.0f - wx);
        float w01 = (1.0f - wy) * wx;
        float w10 = wy * (1.0f - wx);
        float w11 = wy * wx;

        // pair-load: pixels (x0, x0+1) are 64B contiguous
        const uint4* r0 = g_planeH + (size_t)((p * RES + y0) * RES + x0) * 2;
        const uint4* r1 = g_planeH + (size_t)((p * RES + y1) * RES + x0) * 2;
        uint4 rowA[4] = { r0[0], r0[1], r0[2], r0[3] };
        uint4 rowB[4] = { r1[0], r1[1], r1[2], r1[3] };

        float il = (lc + 1.0f) * 0.5f * (float)(RES - 1);
        float fl = floorf(il);
        float wl = il - fl;
        int l0 = min(max((int)fl, 0), RES - 1);
        const uint4* lr = g_lineH + (size_t)(p * RES + l0) * 2;
        uint4 rowL[4] = { lr[0], lr[1], lr[2], lr[3] };

        const __half2* h00 = reinterpret_cast<const __half2*>(&rowA[0]);
        const __half2* h01 = reinterpret_cast<const __half2*>(&rowA[2]);
        const __half2* h10 = reinterpret_cast<const __half2*>(&rowB[0]);
        const __half2* h11 = reinterpret_cast<const __half2*>(&rowB[2]);
        const __half2* hl0 = reinterpret_cast<const __half2*>(&rowL[0]);
        const __half2* hl1 = reinterpret_cast<const __half2*>(&rowL[2]);

        float omwl = 1.0f - wl;

#pragma unroll
        for (int k = 0; k < 8; ++k) {
            float2 f00 = __half22float2(h00[k]);
            float2 f01 = __half22float2(h01[k]);
            float2 f10 = __half22float2(h10[k]);
            float2 f11 = __half22float2(h11[k]);
            float px = fmaf(f00.x, w00, fmaf(f01.x, w01, fmaf(f10.x, w10, f11.x * w11)));
            float py = fmaf(f00.y, w00, fmaf(f01.y, w01, fmaf(f10.y, w10, f11.y * w11)));

            float2 g0 = __half22float2(hl0[k]);
            float2 g1 = __half22float2(hl1[k]);
            float lx = fmaf(g0.x, omwl, g1.x * wl);
            float ly = fmaf(g0.y, omwl, g1.y * wl);

            coef[k].x = fmaf(px, lx, coef[k].x);
            coef[k].y = fmaf(py, ly, coef[k].y);
        }
    }

    // pfeat = _sample1d(params_grid [3,3], t)
    float t  = s_ts[threadIdx.x];
    float it = (t + 1.0f) * 0.5f * 2.0f;
    float ft = floorf(it);
    float wt = it - ft;
    int a0 = min(max((int)ft, 0), 2);
    int a1 = min(a0 + 1, 2);
    float pf[3];
#pragma unroll
    for (int j = 0; j < 3; ++j)
        pf[j] = fmaf(__ldg(&params[j * 3 + a0]), 1.0f - wt,
                     __ldg(&params[j * 3 + a1]) * wt);

    float cf[NCOMP];
#pragma unroll
    for (int k = 0; k < 8; ++k) {
        cf[2 * k + 0] = coef[k].x;
        cf[2 * k + 1] = coef[k].y;
    }

    float* op = out + (size_t)i * NOUT;
#pragma unroll
    for (int o4 = 0; o4 < NOUT / 4; ++o4) {
        float4 r;
        float* rr = reinterpret_cast<float*>(&r);
#pragma unroll
        for (int kk = 0; kk < 4; ++kk) {
            int o = o4 * 4 + kk;
            float acc = 0.0f;
#pragma unroll
            for (int c = 0; c < NCOMP; ++c)
                acc = fmaf(cf[c], sW[o * NIN + c], acc);
#pragma unroll
            for (int j = 0; j < 3; ++j)
                acc = fmaf(pf[j], sW[o * NIN + NCOMP + j], acc);
            rr[kk] = acc;
        }
        reinterpret_cast<float4*>(op)[o4] = r;
    }
}

// ---------------------------------------------------------------------------
extern "C" void kernel_launch(void* const* d_in, const int* in_sizes, int n_in,
                              void* d_out, int out_size) {
    const float* pts    = (const float*)d_in[0];
    const float* ts     = (const float*)d_in[1];
    const float* planes = (const float*)d_in[2];
    const float* lines  = (const float*)d_in[3];
    const float* params = (const float*)d_in[4];
    const float* W      = (const float*)d_in[5];
    float* out = (float*)d_out;

    int n = in_sizes[0] / 3;

    k_transpose_planes<<<(3 * RES * RES + 255) / 256, 256>>>(planes);
    k_transpose_lines<<<(3 * RES + 255) / 256, 256>>>(lines);
    k_visnerf<<<(n + 255) / 256, 256>>>(pts, ts, params, W, out, n);
}